// round 2
// baseline (speedup 1.0000x reference)
#include <cuda_runtime.h>
#include <cuda_bf16.h>

#define NB    4096
#define NT    200
#define ND    64
#define NH1   128
#define NH2   64
#define NTHREADS 512
#define NWARP 16

struct Smem {
    float c[ND];                  // candidate embedding
    float u[NH1];                 // b1 + cand @ (W1a + W1c)
    float Weff[ND][NH1];          // W1b - W1c + diag(c) W1d
    float W2s[NH1][NH2];
    float w3s[NH2];
    float hist[NT][ND];           // history tile (fp32)
    float h1buf[NWARP][4][NH1];   // per-warp layer-1 staging
    float scores[NT];
    float weights[NT];
    float invsum;
    float partial[8][ND];
};

__global__ void __launch_bounds__(NTHREADS, 1)
attention_unit_kernel(const float* __restrict__ cand_g,
                      const float* __restrict__ hist_g,
                      const int*   __restrict__ mask_g,
                      const float* __restrict__ W1,
                      const float* __restrict__ b1,
                      const float* __restrict__ W2,
                      const float* __restrict__ b2,
                      const float* __restrict__ W3,
                      const float* __restrict__ b3,
                      float* __restrict__ out)
{
    extern __shared__ char smem_raw[];
    Smem& s = *reinterpret_cast<Smem*>(smem_raw);

    const int b    = blockIdx.x;
    const int tid  = threadIdx.x;
    const int warp = tid >> 5;
    const int lane = tid & 31;

    // ---- stage candidate ----
    if (tid < ND) s.c[tid] = cand_g[(size_t)b * ND + tid];

    // ---- stage history (coalesced float4) ----
    {
        const float4* hg = reinterpret_cast<const float4*>(hist_g + (size_t)b * NT * ND);
        float4* hs = reinterpret_cast<float4*>(&s.hist[0][0]);
        #pragma unroll 2
        for (int i = tid; i < NT * ND / 4; i += NTHREADS) hs[i] = hg[i];
    }

    // ---- stage W2, W3 ----
    for (int i = tid; i < NH1 * NH2; i += NTHREADS) (&s.W2s[0][0])[i] = W2[i];
    if (tid < NH2) s.w3s[tid] = W3[tid];

    __syncthreads();  // c visible for Weff / u

    // ---- W_eff[d][h] = W1[64+d][h] - W1[128+d][h] + c[d]*W1[192+d][h] ----
    for (int e = tid; e < ND * NH1; e += NTHREADS) {
        int d = e >> 7, h = e & 127;
        float cd = s.c[d];
        s.Weff[d][h] = W1[(64 + d) * NH1 + h]
                     - W1[(128 + d) * NH1 + h]
                     + cd * W1[(192 + d) * NH1 + h];
    }
    // ---- u[h] = b1[h] + sum_d c[d]*(W1[d][h] + W1[128+d][h]) ----
    if (tid < NH1) {
        float acc = b1[tid];
        #pragma unroll 4
        for (int d = 0; d < ND; d++)
            acc += s.c[d] * (W1[d * NH1 + tid] + W1[(128 + d) * NH1 + tid]);
        s.u[tid] = acc;
    }
    __syncthreads();

    // ---- per-warp: GEMM1 (4t x 128h) -> relu -> GEMM2 (4t x 64) -> GEMM3 -> scores ----
    const float  b3v = b3[0];
    const float2 b2v = *reinterpret_cast<const float2*>(&b2[lane << 1]);
    const float  w3a = s.w3s[lane << 1];
    const float  w3b = s.w3s[(lane << 1) + 1];

    for (int base = warp * 4; base < NT; base += NWARP * 4) {
        // GEMM1: h1[t][h] = relu( hist[t][:] @ Weff[:, h] + u[h] )
        float acc[4][4];
        #pragma unroll
        for (int ti = 0; ti < 4; ti++)
            #pragma unroll
            for (int j = 0; j < 4; j++) acc[ti][j] = 0.f;

        #pragma unroll 4
        for (int k = 0; k < ND; k++) {
            float4 wv = *reinterpret_cast<const float4*>(&s.Weff[k][lane << 2]);
            float a0 = s.hist[base + 0][k];
            float a1 = s.hist[base + 1][k];
            float a2 = s.hist[base + 2][k];
            float a3 = s.hist[base + 3][k];
            acc[0][0] += a0 * wv.x; acc[0][1] += a0 * wv.y; acc[0][2] += a0 * wv.z; acc[0][3] += a0 * wv.w;
            acc[1][0] += a1 * wv.x; acc[1][1] += a1 * wv.y; acc[1][2] += a1 * wv.z; acc[1][3] += a1 * wv.w;
            acc[2][0] += a2 * wv.x; acc[2][1] += a2 * wv.y; acc[2][2] += a2 * wv.z; acc[2][3] += a2 * wv.w;
            acc[3][0] += a3 * wv.x; acc[3][1] += a3 * wv.y; acc[3][2] += a3 * wv.z; acc[3][3] += a3 * wv.w;
        }
        {
            float4 uv = *reinterpret_cast<const float4*>(&s.u[lane << 2]);
            #pragma unroll
            for (int ti = 0; ti < 4; ti++) {
                float4 hv;
                hv.x = fmaxf(acc[ti][0] + uv.x, 0.f);
                hv.y = fmaxf(acc[ti][1] + uv.y, 0.f);
                hv.z = fmaxf(acc[ti][2] + uv.z, 0.f);
                hv.w = fmaxf(acc[ti][3] + uv.w, 0.f);
                *reinterpret_cast<float4*>(&s.h1buf[warp][ti][lane << 2]) = hv;
            }
        }
        __syncwarp();

        // GEMM2: h2[t][j] = relu( h1[t][:] @ W2[:, j] + b2[j] ), j = lane*2 + {0,1}
        float acc2[4][2];
        #pragma unroll
        for (int ti = 0; ti < 4; ti++) { acc2[ti][0] = b2v.x; acc2[ti][1] = b2v.y; }

        #pragma unroll 4
        for (int k = 0; k < NH1; k++) {
            float2 w2v = *reinterpret_cast<const float2*>(&s.W2s[k][lane << 1]);
            float a0 = s.h1buf[warp][0][k];
            float a1 = s.h1buf[warp][1][k];
            float a2 = s.h1buf[warp][2][k];
            float a3 = s.h1buf[warp][3][k];
            acc2[0][0] += a0 * w2v.x; acc2[0][1] += a0 * w2v.y;
            acc2[1][0] += a1 * w2v.x; acc2[1][1] += a1 * w2v.y;
            acc2[2][0] += a2 * w2v.x; acc2[2][1] += a2 * w2v.y;
            acc2[3][0] += a3 * w2v.x; acc2[3][1] += a3 * w2v.y;
        }

        // GEMM3 + warp reduction -> scores
        float p[4];
        #pragma unroll
        for (int ti = 0; ti < 4; ti++)
            p[ti] = fmaxf(acc2[ti][0], 0.f) * w3a + fmaxf(acc2[ti][1], 0.f) * w3b;
        #pragma unroll
        for (int o = 16; o; o >>= 1) {
            p[0] += __shfl_xor_sync(0xFFFFFFFFu, p[0], o);
            p[1] += __shfl_xor_sync(0xFFFFFFFFu, p[1], o);
            p[2] += __shfl_xor_sync(0xFFFFFFFFu, p[2], o);
            p[3] += __shfl_xor_sync(0xFFFFFFFFu, p[3], o);
        }
        if (lane == 0) {
            s.scores[base + 0] = p[0] + b3v;
            s.scores[base + 1] = p[1] + b3v;
            s.scores[base + 2] = p[2] + b3v;
            s.scores[base + 3] = p[3] + b3v;
        }
        __syncwarp();
    }
    __syncthreads();

    // ---- mask ----
    if (tid < NT) {
        float sc = s.scores[tid];
        if (mask_g[(size_t)b * NT + tid] == 0) sc = -1.0e9f;
        s.scores[tid] = sc;
    }
    __syncthreads();

    // ---- softmax (warp 0) ----
    if (tid < 32) {
        float m = -3.4e38f;
        for (int t = tid; t < NT; t += 32) m = fmaxf(m, s.scores[t]);
        #pragma unroll
        for (int o = 16; o; o >>= 1) m = fmaxf(m, __shfl_xor_sync(0xFFFFFFFFu, m, o));
        float sum = 0.f;
        for (int t = tid; t < NT; t += 32) {
            float e = __expf(s.scores[t] - m);
            s.weights[t] = e;
            sum += e;
        }
        #pragma unroll
        for (int o = 16; o; o >>= 1) sum += __shfl_xor_sync(0xFFFFFFFFu, sum, o);
        if (tid == 0) s.invsum = 1.0f / sum;
    }
    __syncthreads();

    // ---- out[b][d] = invsum * sum_t hist[t][d] * w[t] ----
    {
        int d = tid & (ND - 1);
        int g = tid >> 6;          // 8 groups
        float acc = 0.f;
        for (int t = g; t < NT; t += 8) acc += s.hist[t][d] * s.weights[t];
        s.partial[g][d] = acc;
    }
    __syncthreads();
    if (tid < ND) {
        float o = 0.f;
        #pragma unroll
        for (int g = 0; g < 8; g++) o += s.partial[g][tid];
        out[(size_t)b * ND + tid] = o * s.invsum;
    }
}

extern "C" void kernel_launch(void* const* d_in, const int* in_sizes, int n_in,
                              void* d_out, int out_size)
{
    const float* cand = (const float*)d_in[0];
    const float* hist = (const float*)d_in[1];
    const int*   mask = (const int*)  d_in[2];
    const float* W1   = (const float*)d_in[3];
    const float* b1   = (const float*)d_in[4];
    const float* W2   = (const float*)d_in[5];
    const float* b2   = (const float*)d_in[6];
    const float* W3   = (const float*)d_in[7];
    const float* b3   = (const float*)d_in[8];
    float* out        = (float*)d_out;

    const int smem = (int)sizeof(Smem);
    cudaFuncSetAttribute(attention_unit_kernel,
                         cudaFuncAttributeMaxDynamicSharedMemorySize, smem);

    attention_unit_kernel<<<NB, NTHREADS, smem>>>(cand, hist, mask, W1, b1, W2, b2, W3, b3, out);
}

// round 4
// speedup vs baseline: 1.1698x; 1.1698x over previous
#include <cuda_runtime.h>
#include <cuda_bf16.h>

#define NB    4096
#define NT    200
#define ND    64
#define NH1   128
#define NH2   64
#define NTHREADS 800          // 25 warps: exactly one 8-row tile per warp per phase
#define NTILES   25
#define W2T_STRIDE 132        // pad: stride*4B mod 128B = 16B -> conflict-free float4 pattern

struct Smem {
    float hist[NT][ND];            // 51200 B
    float Weff[ND][NH1];           // 32768 B
    float W2T[NH2][W2T_STRIDE];    // 33792 B  (W2 transposed, k-contiguous)
    float h1all[NT][NH1];          // 102400 B
    float c[ND];
    float u[NH1];
    float scores[NT];
    float weights[NT];
    float partial[12][ND];
    float invsum;
};

__global__ void __launch_bounds__(NTHREADS, 1)
attention_unit_kernel(const float* __restrict__ cand_g,
                      const float* __restrict__ hist_g,
                      const int*   __restrict__ mask_g,
                      const float* __restrict__ W1,
                      const float* __restrict__ b1,
                      const float* __restrict__ W2,
                      const float* __restrict__ b2,
                      const float* __restrict__ W3,
                      const float* __restrict__ b3,
                      float* __restrict__ out)
{
    extern __shared__ char smem_raw[];
    Smem& s = *reinterpret_cast<Smem*>(smem_raw);

    const int b    = blockIdx.x;
    const int tid  = threadIdx.x;
    const int warp = tid >> 5;
    const int lane = tid & 31;

    // ---- stage candidate ----
    if (tid < ND) s.c[tid] = cand_g[(size_t)b * ND + tid];

    // ---- stage history (coalesced float4: 3200 vecs / 800 thr = 4 iters) ----
    {
        const float4* hg = reinterpret_cast<const float4*>(hist_g + (size_t)b * NT * ND);
        float4* hs = reinterpret_cast<float4*>(&s.hist[0][0]);
        #pragma unroll
        for (int i = 0; i < 4; i++) hs[tid + i * NTHREADS] = hg[tid + i * NTHREADS];
    }

    // ---- stage W2 transposed: W2T[j][k] = W2[k][j] ----
    for (int i = tid; i < NH1 * NH2; i += NTHREADS) {
        int k = i >> 6, j = i & 63;
        s.W2T[j][k] = W2[i];
    }

    __syncthreads();   // c visible

    // ---- Weff[d][h] = W1[64+d][h] - W1[128+d][h] + c[d]*W1[192+d][h] ----
    for (int e = tid; e < ND * NH1; e += NTHREADS) {
        int d = e >> 7, h = e & 127;
        s.Weff[d][h] = W1[(64 + d) * NH1 + h]
                     - W1[(128 + d) * NH1 + h]
                     + s.c[d] * W1[(192 + d) * NH1 + h];
    }
    // ---- u[h] = b1[h] + sum_d c[d]*(W1[d][h] + W1[128+d][h]) ----
    if (tid < NH1) {
        float acc = b1[tid];
        #pragma unroll 4
        for (int d = 0; d < ND; d++)
            acc += s.c[d] * (W1[d * NH1 + tid] + W1[(128 + d) * NH1 + tid]);
        s.u[tid] = acc;
    }
    __syncthreads();

    // ================= Phase A: GEMM1, one 8t x 128h tile per warp =================
    {
        const int base = warp * 8;           // warp < 25 always
        float acc[8][4];
        #pragma unroll
        for (int t = 0; t < 8; t++)
            #pragma unroll
            for (int j = 0; j < 4; j++) acc[t][j] = 0.f;

        #pragma unroll 4
        for (int k = 0; k < ND; k += 2) {
            float4 w0 = *reinterpret_cast<const float4*>(&s.Weff[k + 0][lane << 2]);
            float4 w1 = *reinterpret_cast<const float4*>(&s.Weff[k + 1][lane << 2]);
            #pragma unroll
            for (int t = 0; t < 8; t++) {
                float2 h = *reinterpret_cast<const float2*>(&s.hist[base + t][k]);
                acc[t][0] += h.x * w0.x; acc[t][1] += h.x * w0.y;
                acc[t][2] += h.x * w0.z; acc[t][3] += h.x * w0.w;
                acc[t][0] += h.y * w1.x; acc[t][1] += h.y * w1.y;
                acc[t][2] += h.y * w1.z; acc[t][3] += h.y * w1.w;
            }
        }
        float4 uv = *reinterpret_cast<const float4*>(&s.u[lane << 2]);
        #pragma unroll
        for (int t = 0; t < 8; t++) {
            float4 hv;
            hv.x = fmaxf(acc[t][0] + uv.x, 0.f);
            hv.y = fmaxf(acc[t][1] + uv.y, 0.f);
            hv.z = fmaxf(acc[t][2] + uv.z, 0.f);
            hv.w = fmaxf(acc[t][3] + uv.w, 0.f);
            *reinterpret_cast<float4*>(&s.h1all[base + t][lane << 2]) = hv;
        }
    }
    __syncthreads();

    // ============ Phase B: GEMM2+GEMM3, one 8t tile per warp; lane owns j, j+32 ============
    {
        const int base = warp * 8;
        const int j0 = lane, j1 = lane + 32;
        const float b20 = b2[j0], b21 = b2[j1];
        const float w30 = W3[j0], w31 = W3[j1];
        const float b3v = b3[0];

        float a0[8], a1[8];
        #pragma unroll
        for (int t = 0; t < 8; t++) { a0[t] = b20; a1[t] = b21; }

        #pragma unroll 4
        for (int k = 0; k < NH1; k += 4) {
            float4 wa = *reinterpret_cast<const float4*>(&s.W2T[j0][k]);
            float4 wb = *reinterpret_cast<const float4*>(&s.W2T[j1][k]);
            #pragma unroll
            for (int t = 0; t < 8; t++) {
                float4 h = *reinterpret_cast<const float4*>(&s.h1all[base + t][k]);
                a0[t] += h.x * wa.x + h.y * wa.y + h.z * wa.z + h.w * wa.w;
                a1[t] += h.x * wb.x + h.y * wb.y + h.z * wb.z + h.w * wb.w;
            }
        }

        float p[8];
        #pragma unroll
        for (int t = 0; t < 8; t++)
            p[t] = fmaxf(a0[t], 0.f) * w30 + fmaxf(a1[t], 0.f) * w31;
        #pragma unroll
        for (int o = 16; o; o >>= 1)
            #pragma unroll
            for (int t = 0; t < 8; t++)
                p[t] += __shfl_xor_sync(0xFFFFFFFFu, p[t], o);
        if (lane < 8) s.scores[base + lane] = p[lane] + b3v;   // lane t holds same reduced value? no:
        // NOTE: after xor-reduction every lane holds the full sum for each t, so lane<8 writes p[lane]... 
        // but p[t] per-lane are t-indexed, all lanes identical -> lane L writes t=L's value: correct.
    }
    __syncthreads();

    // ---- mask ----
    if (tid < NT) {
        float sc = s.scores[tid];
        if (mask_g[(size_t)b * NT + tid] == 0) sc = -1.0e9f;
        s.scores[tid] = sc;
    }
    __syncthreads();

    // ---- softmax (warp 0) ----
    if (tid < 32) {
        float m = -3.4e38f;
        for (int t = tid; t < NT; t += 32) m = fmaxf(m, s.scores[t]);
        #pragma unroll
        for (int o = 16; o; o >>= 1) m = fmaxf(m, __shfl_xor_sync(0xFFFFFFFFu, m, o));
        float sum = 0.f;
        for (int t = tid; t < NT; t += 32) {
            float e = __expf(s.scores[t] - m);
            s.weights[t] = e;
            sum += e;
        }
        #pragma unroll
        for (int o = 16; o; o >>= 1) sum += __shfl_xor_sync(0xFFFFFFFFu, sum, o);
        if (tid == 0) s.invsum = 1.0f / sum;
    }
    __syncthreads();

    // ---- out[b][d] = invsum * sum_t hist[t][d] * w[t]  (12 groups x 64 d = 768 thr) ----
    if (tid < 768) {
        int d = tid & (ND - 1);
        int g = tid >> 6;
        float acc = 0.f;
        for (int t = g; t < NT; t += 12) acc += s.hist[t][d] * s.weights[t];
        s.partial[g][d] = acc;
    }
    __syncthreads();
    if (tid < ND) {
        float o = 0.f;
        #pragma unroll
        for (int g = 0; g < 12; g++) o += s.partial[g][tid];
        out[(size_t)b * ND + tid] = o * s.invsum;
    }
}

extern "C" void kernel_launch(void* const* d_in, const int* in_sizes, int n_in,
                              void* d_out, int out_size)
{
    const float* cand = (const float*)d_in[0];
    const float* hist = (const float*)d_in[1];
    const int*   mask = (const int*)  d_in[2];
    const float* W1   = (const float*)d_in[3];
    const float* b1   = (const float*)d_in[4];
    const float* W2   = (const float*)d_in[5];
    const float* b2   = (const float*)d_in[6];
    const float* W3   = (const float*)d_in[7];
    const float* b3   = (const float*)d_in[8];
    float* out        = (float*)d_out;

    const int smem = (int)sizeof(Smem);
    cudaFuncSetAttribute(attention_unit_kernel,
                         cudaFuncAttributeMaxDynamicSharedMemorySize, smem);

    attention_unit_kernel<<<NB, NTHREADS, smem>>>(cand, hist, mask, W1, b1, W2, b2, W3, b3, out);
}

// round 8
// speedup vs baseline: 1.9681x; 1.6823x over previous
#include <cuda_runtime.h>
#include <cuda_bf16.h>
#include <cstdint>

#define NB 4096
#define NT 200
#define ND 64
#define NH1 128
#define NH2 64
#define NTHREADS 512

// All operand tiles use natural row pitch (128B or 256B) with a per-row
// chunk-XOR swizzle: physical_16B_chunk = logical_chunk ^ (row & 7).
// Conflict-free for ldmatrix 8-row phases and for all epilogue stores.
struct __align__(16) Smem {
    char Ahi[208 * 128];   // hist hi  [208 rows][64 bf16]
    char Alo[208 * 128];
    char B1hi[128 * 128];  // Weff^T   [128 n][64 k]
    char B1lo[128 * 128];
    char Hhi[208 * 256];   // layer-1 out [208 rows][128 bf16]
    char Hlo[208 * 256];
    char B2hi[64 * 256];   // W2^T     [64 n][128 k]
    char B2lo[64 * 256];
    float u[NH1];
    float b2s[NH2], w3s[NH2];
    float scores[208];
    float weights[NT];
    float partial[8][ND];
    float invsum;
};

__device__ __forceinline__ uint32_t smem_u32(const void* p) {
    uint32_t a;
    asm("{ .reg .u64 t; cvta.to.shared.u64 t, %1; cvt.u32.u64 %0, t; }" : "=r"(a) : "l"(p));
    return a;
}
__device__ __forceinline__ void ldsm4(uint32_t* r, uint32_t addr) {
    asm volatile("ldmatrix.sync.aligned.m8n8.x4.shared.b16 {%0,%1,%2,%3}, [%4];"
        : "=r"(r[0]), "=r"(r[1]), "=r"(r[2]), "=r"(r[3]) : "r"(addr));
}
__device__ __forceinline__ void mma16816(float* c, const uint32_t* a, const uint32_t* b) {
    asm volatile("mma.sync.aligned.m16n8k16.row.col.f32.bf16.bf16.f32 "
        "{%0,%1,%2,%3}, {%4,%5,%6,%7}, {%8,%9}, {%0,%1,%2,%3};"
        : "+f"(c[0]), "+f"(c[1]), "+f"(c[2]), "+f"(c[3])
        : "r"(a[0]), "r"(a[1]), "r"(a[2]), "r"(a[3]), "r"(b[0]), "r"(b[1]));
}
__device__ __forceinline__ void split_pair(float x0, float x1, uint32_t& hi, uint32_t& lo) {
    __nv_bfloat16 h0 = __float2bfloat16_rn(x0);
    __nv_bfloat16 h1 = __float2bfloat16_rn(x1);
    float r0 = x0 - __bfloat162float(h0);
    float r1 = x1 - __bfloat162float(h1);
    __nv_bfloat162 H; H.x = h0; H.y = h1;
    __nv_bfloat162 L = __floats2bfloat162_rn(r0, r1);
    hi = *reinterpret_cast<uint32_t*>(&H);
    lo = *reinterpret_cast<uint32_t*>(&L);
}
__device__ __forceinline__ void split_one(float x, uint16_t& hi, uint16_t& lo) {
    __nv_bfloat16 h = __float2bfloat16_rn(x);
    __nv_bfloat16 l = __float2bfloat16_rn(x - __bfloat162float(h));
    hi = *reinterpret_cast<uint16_t*>(&h);
    lo = *reinterpret_cast<uint16_t*>(&l);
}

__global__ void __launch_bounds__(NTHREADS, 1)
attention_unit_kernel(const float* __restrict__ cand_g,
                      const float* __restrict__ hist_g,
                      const int*   __restrict__ mask_g,
                      const float* __restrict__ W1,
                      const float* __restrict__ b1,
                      const float* __restrict__ W2,
                      const float* __restrict__ b2,
                      const float* __restrict__ W3,
                      const float* __restrict__ b3,
                      float* __restrict__ out)
{
    extern __shared__ __align__(16) char smem_raw[];
    Smem& s = *reinterpret_cast<Smem*>(smem_raw);

    const int b    = blockIdx.x;
    const int tid  = threadIdx.x;
    const int warp = tid >> 5;
    const int lane = tid & 31;

    // =================== Phase 0: stage + split everything ===================
    // hist -> Ahi/Alo (bf16 hi/lo, swizzled)
    {
        const float4* hg = reinterpret_cast<const float4*>(hist_g + (size_t)b * NT * ND);
        for (int i = tid; i < NT * ND / 4; i += NTHREADS) {
            float4 v = hg[i];
            int t = i >> 4, q = i & 15;              // q -> elements 4q..4q+3
            uint32_t h01, l01, h23, l23;
            split_pair(v.x, v.y, h01, l01);
            split_pair(v.z, v.w, h23, l23);
            uint32_t off = (uint32_t)(t * 128 + (((q >> 1) ^ (t & 7)) << 4) + (q & 1) * 8);
            *reinterpret_cast<uint2*>(s.Ahi + off) = make_uint2(h01, h23);
            *reinterpret_cast<uint2*>(s.Alo + off) = make_uint2(l01, l23);
        }
        // zero pad rows 200..207
        for (int i = tid; i < 8 * 128 / 8; i += NTHREADS) {
            reinterpret_cast<uint2*>(s.Ahi + 200 * 128)[i] = make_uint2(0, 0);
            reinterpret_cast<uint2*>(s.Alo + 200 * 128)[i] = make_uint2(0, 0);
        }
    }
    // Weff^T[h][d] = W1[64+d][h] - W1[128+d][h] + c[d]*W1[192+d][h]
    {
        int h = tid & 127, dg = tid >> 7;
        #pragma unroll 4
        for (int dd = 0; dd < 16; dd++) {
            int d = dg * 16 + dd;
            float cd = __ldg(&cand_g[(size_t)b * ND + d]);
            float w = W1[(64 + d) * NH1 + h] - W1[(128 + d) * NH1 + h]
                    + cd * W1[(192 + d) * NH1 + h];
            uint16_t hi, lo; split_one(w, hi, lo);
            uint32_t off = (uint32_t)(h * 128 + (((d >> 3) ^ (h & 7)) << 4) + (d & 7) * 2);
            *reinterpret_cast<uint16_t*>(s.B1hi + off) = hi;
            *reinterpret_cast<uint16_t*>(s.B1lo + off) = lo;
        }
    }
    // u[h] = b1[h] + sum_d c[d]*(W1[d][h] + W1[128+d][h])
    if (tid < NH1) {
        float acc = b1[tid];
        #pragma unroll 4
        for (int d = 0; d < ND; d++)
            acc += __ldg(&cand_g[(size_t)b * ND + d])
                 * (W1[d * NH1 + tid] + W1[(128 + d) * NH1 + tid]);
        s.u[tid] = acc;
    }
    // W2^T[j][k]
    {
        int j = tid & 63, kg = tid >> 6;
        #pragma unroll 4
        for (int kk = 0; kk < 16; kk++) {
            int k = kg * 16 + kk;
            uint16_t hi, lo; split_one(W2[k * NH2 + j], hi, lo);
            uint32_t off = (uint32_t)(j * 256 + (((k >> 3) ^ (j & 7)) << 4) + (k & 7) * 2);
            *reinterpret_cast<uint16_t*>(s.B2hi + off) = hi;
            *reinterpret_cast<uint16_t*>(s.B2lo + off) = lo;
        }
    }
    if (tid < NH2) { s.b2s[tid] = b2[tid]; s.w3s[tid] = W3[tid]; }
    if (tid < NT)  s.scores[tid] = b3[0];
    __syncthreads();

    const uint32_t pAhi = smem_u32(s.Ahi), pAlo = smem_u32(s.Alo);
    const uint32_t pB1h = smem_u32(s.B1hi), pB1l = smem_u32(s.B1lo);
    const uint32_t pHhi = smem_u32(s.Hhi), pHlo = smem_u32(s.Hlo);
    const uint32_t pB2h = smem_u32(s.B2hi), pB2l = smem_u32(s.B2lo);

    const int lrow = lane & 15, lkh = lane >> 4;          // A ldmatrix pattern
    const int bn   = ((lane >> 4) << 3) + (lane & 7);     // B ldmatrix row
    const int bk   = (lane >> 3) & 1;                     // B ldmatrix k-half

    // =================== GEMM1: 52 tasks of m16 x n32, k=64 ===================
    for (int tsk = warp; tsk < 52; tsk += 16) {
        int mt = tsk >> 2, nt = tsk & 3;
        float acc[16];
        #pragma unroll
        for (int i = 0; i < 16; i++) acc[i] = 0.f;
        int arow = mt * 16 + lrow;

        #pragma unroll
        for (int kk = 0; kk < 4; kk++) {
            uint32_t ra[4], rl[4], rbh[2][4], rbl[2][4];
            uint32_t aoff = (uint32_t)(arow * 128 + (((kk * 2 + lkh) ^ (arow & 7)) << 4));
            ldsm4(ra, pAhi + aoff);
            ldsm4(rl, pAlo + aoff);
            #pragma unroll
            for (int p = 0; p < 2; p++) {
                int brow = nt * 32 + p * 16 + bn;
                uint32_t boff = (uint32_t)(brow * 128 + (((kk * 2 + bk) ^ (brow & 7)) << 4));
                ldsm4(rbh[p], pB1h + boff);
                ldsm4(rbl[p], pB1l + boff);
            }
            #pragma unroll
            for (int f = 0; f < 4; f++) {
                const uint32_t* bh = &rbh[f >> 1][(f & 1) * 2];
                const uint32_t* bl = &rbl[f >> 1][(f & 1) * 2];
                mma16816(acc + f * 4, ra, bh);
                mma16816(acc + f * 4, ra, bl);
                mma16816(acc + f * 4, rl, bh);
            }
        }
        // epilogue: +u, relu, split, store H (rows rlo, rlo+8)
        int rlo = mt * 16 + (lane >> 2);
        #pragma unroll
        for (int f = 0; f < 4; f++) {
            int col = nt * 32 + f * 8 + (lane & 3) * 2;
            float u0 = s.u[col], u1 = s.u[col + 1];
            uint32_t h0, l0, h1, l1;
            split_pair(fmaxf(acc[f * 4 + 0] + u0, 0.f), fmaxf(acc[f * 4 + 1] + u1, 0.f), h0, l0);
            split_pair(fmaxf(acc[f * 4 + 2] + u0, 0.f), fmaxf(acc[f * 4 + 3] + u1, 0.f), h1, l1);
            int ch = col >> 3, wb = (col & 7) * 2;
            uint32_t o0 = (uint32_t)(rlo * 256 + ((ch ^ (rlo & 7)) << 4) + wb);
            uint32_t o1 = o0 + 8 * 256;
            *reinterpret_cast<uint32_t*>(s.Hhi + o0) = h0;
            *reinterpret_cast<uint32_t*>(s.Hhi + o1) = h1;
            *reinterpret_cast<uint32_t*>(s.Hlo + o0) = l0;
            *reinterpret_cast<uint32_t*>(s.Hlo + o1) = l1;
        }
    }
    __syncthreads();

    // =================== GEMM2: 26 tasks of m16 x n32, k=128 ===================
    for (int tsk = warp; tsk < 26; tsk += 16) {
        int mt = tsk >> 1, nt = tsk & 1;
        float acc[16];
        #pragma unroll
        for (int i = 0; i < 16; i++) acc[i] = 0.f;
        int arow = mt * 16 + lrow;

        #pragma unroll
        for (int kk = 0; kk < 8; kk++) {
            uint32_t ra[4], rl[4], rbh[2][4], rbl[2][4];
            uint32_t aoff = (uint32_t)(arow * 256 + (((kk * 2 + lkh) ^ (arow & 7)) << 4));
            ldsm4(ra, pHhi + aoff);
            ldsm4(rl, pHlo + aoff);
            #pragma unroll
            for (int p = 0; p < 2; p++) {
                int brow = nt * 32 + p * 16 + bn;
                uint32_t boff = (uint32_t)(brow * 256 + (((kk * 2 + bk) ^ (brow & 7)) << 4));
                ldsm4(rbh[p], pB2h + boff);
                ldsm4(rbl[p], pB2l + boff);
            }
            #pragma unroll
            for (int f = 0; f < 4; f++) {
                const uint32_t* bh = &rbh[f >> 1][(f & 1) * 2];
                const uint32_t* bl = &rbl[f >> 1][(f & 1) * 2];
                mma16816(acc + f * 4, ra, bh);
                mma16816(acc + f * 4, ra, bl);
                mma16816(acc + f * 4, rl, bh);
            }
        }
        // epilogue: relu(.+b2) . w3, quad-reduce, atomic into scores
        float vlo = 0.f, vhi = 0.f;
        #pragma unroll
        for (int f = 0; f < 4; f++) {
            int col = nt * 32 + f * 8 + (lane & 3) * 2;
            float b20 = s.b2s[col], b21 = s.b2s[col + 1];
            float w30 = s.w3s[col], w31 = s.w3s[col + 1];
            vlo += fmaxf(acc[f * 4 + 0] + b20, 0.f) * w30 + fmaxf(acc[f * 4 + 1] + b21, 0.f) * w31;
            vhi += fmaxf(acc[f * 4 + 2] + b20, 0.f) * w30 + fmaxf(acc[f * 4 + 3] + b21, 0.f) * w31;
        }
        vlo += __shfl_xor_sync(0xFFFFFFFFu, vlo, 1);
        vlo += __shfl_xor_sync(0xFFFFFFFFu, vlo, 2);
        vhi += __shfl_xor_sync(0xFFFFFFFFu, vhi, 1);
        vhi += __shfl_xor_sync(0xFFFFFFFFu, vhi, 2);
        if ((lane & 3) == 0) {
            int rlo = mt * 16 + (lane >> 2);
            atomicAdd(&s.scores[rlo], vlo);
            int rhi = rlo + 8;
            if (rhi < NT) atomicAdd(&s.scores[rhi], vhi);
        }
    }
    __syncthreads();

    // ---- mask ----
    if (tid < NT) {
        float sc = s.scores[tid];
        if (mask_g[(size_t)b * NT + tid] == 0) sc = -1.0e9f;
        s.scores[tid] = sc;
    }
    __syncthreads();

    // ---- softmax (warp 0) ----
    if (tid < 32) {
        float m = -3.4e38f;
        for (int t = tid; t < NT; t += 32) m = fmaxf(m, s.scores[t]);
        #pragma unroll
        for (int o = 16; o; o >>= 1) m = fmaxf(m, __shfl_xor_sync(0xFFFFFFFFu, m, o));
        float sum = 0.f;
        for (int t = tid; t < NT; t += 32) {
            float e = __expf(s.scores[t] - m);
            s.weights[t] = e;
            sum += e;
        }
        #pragma unroll
        for (int o = 16; o; o >>= 1) sum += __shfl_xor_sync(0xFFFFFFFFu, sum, o);
        if (tid == 0) s.invsum = 1.0f / sum;
    }
    __syncthreads();

    // ---- out[b][d] = invsum * sum_t hist[t][d] * w[t]  (hist reloaded, L2-hot) ----
    {
        int d = tid & (ND - 1);
        int g = tid >> 6;                 // 8 groups
        const float* hb = hist_g + (size_t)b * NT * ND;
        float acc = 0.f;
        for (int t = g; t < NT; t += 8) acc += hb[t * ND + d] * s.weights[t];
        s.partial[g][d] = acc;
    }
    __syncthreads();
    if (tid < ND) {
        float o = 0.f;
        #pragma unroll
        for (int g = 0; g < 8; g++) o += s.partial[g][tid];
        out[(size_t)b * ND + tid] = o * s.invsum;
    }
}

extern "C" void kernel_launch(void* const* d_in, const int* in_sizes, int n_in,
                              void* d_out, int out_size)
{
    const float* cand = (const float*)d_in[0];
    const float* hist = (const float*)d_in[1];
    const int*   mask = (const int*)  d_in[2];
    const float* W1   = (const float*)d_in[3];
    const float* b1   = (const float*)d_in[4];
    const float* W2   = (const float*)d_in[5];
    const float* b2   = (const float*)d_in[6];
    const float* W3   = (const float*)d_in[7];
    const float* b3   = (const float*)d_in[8];
    float* out        = (float*)d_out;

    const int smem = (int)sizeof(Smem);
    cudaFuncSetAttribute(attention_unit_kernel,
                         cudaFuncAttributeMaxDynamicSharedMemorySize, smem);

    attention_unit_kernel<<<NB, NTHREADS, smem>>>(cand, hist, mask, W1, b1, W2, b2, W3, b3, out);
}